// round 12
// baseline (speedup 1.0000x reference)
#include <cuda_runtime.h>
#include <cuda_bf16.h>

// Problem constants (fixed shapes from setup_inputs)
#define B_   32
#define S_   4
#define C_   34      // (1 + TAG_DIM) * N_PARTS
#define NP_  17      // N_PARTS
#define HW_  16384   // 128*128
#define M_   30
#define P_   17

#define HW4_       4096      // HW/4
#define SLICE4_    69632     // NP*HW/4 (det slice per (b,s), in float4)
#define PRED_BS4_  139264    // C*HW/4  (full (b,s) slice stride, in float4)

#define NBLK 8704
#define NTHR 256
#define ITERS 4
// NBLK*NTHR*ITERS == B*S*NP*HW/4 == 8,912,896 exactly

#define DET_ELEMS  35651584.0f   // B*S*NP*HW
#define TAG_ITEMS  65280u        // B*S*M*P

__global__ void init_out_kernel(float* __restrict__ out)
{
    out[0] = 0.0f;   // harness poisons d_out; every replay re-zeros it
}

__global__ __launch_bounds__(NTHR) void loss_fused_kernel(
    const float4* __restrict__ preds4,
    const float4* __restrict__ masks4,
    const int*    __restrict__ kidx,    // JAX downcasts int64 -> int32 (x64 disabled)
    const float*  __restrict__ kvis,
    const float*  __restrict__ gtags,
    const float4* __restrict__ heat4,
    const float*  __restrict__ preds,
    float*        __restrict__ out)
{
    const unsigned gtid   = blockIdx.x * (unsigned)NTHR + threadIdx.x;
    const unsigned stride = (unsigned)NBLK * NTHR;

    // ---- det part: 4 coalesced float4 iterations per thread ----
    float det = 0.0f;
    unsigned v = gtid;
#pragma unroll
    for (int it = 0; it < ITERS; ++it) {
        unsigned bs  = v / SLICE4_;          // (b*S + s)
        unsigned rem = v - bs * SLICE4_;     // vec4 offset within det slice
        unsigned b   = bs >> 2;              // S_ == 4
        // preds: pure single-use stream -> evict-first, keep cache for masks/heat
        float4 p  = __ldcs(&preds4[(size_t)bs * PRED_BS4_ + rem]);
        float4 h  = __ldg (&heat4 [(size_t)b  * SLICE4_   + rem]);
        float4 mk = __ldg (&masks4[(size_t)b  * HW4_ + (rem & (HW4_ - 1u))]);
        float d0 = p.x - h.x, d1 = p.y - h.y, d2 = p.z - h.z, d3 = p.w - h.w;
        det += d0 * d0 * mk.x + d1 * d1 * mk.y + d2 * d2 * mk.z + d3 * d3 * mk.w;
        v += stride;
    }

    // ---- tag part: one gather per low-gtid thread ----
    float tag = 0.0f;
    if (gtid < TAG_ITEMS) {
        unsigned t = gtid;
        unsigned p = t % 17u;
        unsigned m = (t / 17u) % 30u;
        unsigned s = (t / 510u) % 4u;
        unsigned b = t / 2040u;
        unsigned kofs = (b * 30u + m) * 17u + p;   // (B,M,P) layout
        unsigned l = (unsigned)kidx[kofs];         // flattened tag-map index [0, NP*HW)
        size_t addr = ((size_t)(b * 4u + s) * C_ + NP_) * (size_t)HW_ + (size_t)l;
        float pv  = __ldg(preds + addr);
        float g   = gtags[kofs];   // tag_dim==1: (B,1,M,P) == (B,M,P)
        float vis = kvis[kofs];
        float d = pv - g;
        tag = d * d * vis;
    }

    const float DET_SCALE = 1.0f / DET_ELEMS;          // HM_W=1
    const float TAG_SCALE = 0.001f / (float)(B_ * S_); // TAG_W / (B*S)
    float val = det * DET_SCALE + tag * TAG_SCALE;

    // ---- block reduction ----
#pragma unroll
    for (int o = 16; o > 0; o >>= 1)
        val += __shfl_xor_sync(0xffffffffu, val, o);

    __shared__ float ws[NTHR / 32];
    if ((threadIdx.x & 31u) == 0u) ws[threadIdx.x >> 5] = val;
    __syncthreads();

    // one fire-and-forget global atomic per block; no fence, no ticket
    if (threadIdx.x == 0) {
        float x = ws[0];
#pragma unroll
        for (int i = 1; i < NTHR / 32; ++i) x += ws[i];
        atomicAdd(out, x);
    }
}

extern "C" void kernel_launch(void* const* d_in, const int* in_sizes, int n_in,
                              void* d_out, int out_size)
{
    const float4* preds4 = (const float4*)d_in[0];
    const float4* masks4 = (const float4*)d_in[1];
    const int*    kidx   = (const int*)d_in[2];
    const float*  kvis   = (const float*)d_in[3];
    const float*  gtags  = (const float*)d_in[4];
    const float4* heat4  = (const float4*)d_in[5];
    const float*  preds  = (const float*)d_in[0];
    float*        out    = (float*)d_out;

    init_out_kernel<<<1, 1>>>(out);
    loss_fused_kernel<<<NBLK, NTHR>>>(preds4, masks4, kidx, kvis, gtags, heat4, preds, out);
}

// round 13
// speedup vs baseline: 1.1750x; 1.1750x over previous
#include <cuda_runtime.h>
#include <cuda_bf16.h>

// Problem constants (fixed shapes from setup_inputs)
#define B_   32
#define S_   4
#define C_   34      // (1 + TAG_DIM) * N_PARTS
#define NP_  17      // N_PARTS
#define HW_  16384   // 128*128
#define M_   30
#define P_   17

#define HW4_       4096      // HW/4
#define SLICE4_    69632     // NP*HW/4 (det slice per (b,s), in float4)
#define PRED_BS4_  139264    // C*HW/4  (full (b,s) slice stride, in float4)

#define NBLK 8704
#define NTHR 256
// NBLK*NTHR == B * SLICE4_ == 2,228,224 : one thread per (b, det-vec4-position),
// each thread covers all S=4 scales -> heat/mask loaded ONCE per position.

#define DET_ELEMS  35651584.0f   // B*S*NP*HW
#define TAG_ITEMS  65280u        // B*S*M*P

__global__ void init_out_kernel(float* __restrict__ out)
{
    out[0] = 0.0f;   // harness poisons d_out; every replay re-zeros it
}

__global__ __launch_bounds__(NTHR) void loss_fused_kernel(
    const float4* __restrict__ preds4,
    const float4* __restrict__ masks4,
    const int*    __restrict__ kidx,    // JAX downcasts int64 -> int32 (x64 disabled)
    const float*  __restrict__ kvis,
    const float*  __restrict__ gtags,
    const float4* __restrict__ heat4,
    const float*  __restrict__ preds,
    float*        __restrict__ out)
{
    const unsigned gtid = blockIdx.x * (unsigned)NTHR + threadIdx.x;

    // ---- det part: one (b, rem) position, loop over S in registers ----
    const unsigned b   = gtid / SLICE4_;           // batch
    const unsigned rem = gtid - b * SLICE4_;       // vec4 offset within det slice

    const size_t pbase = (size_t)(b * 4u) * PRED_BS4_ + rem;

    // 4 independent preds loads (MLP=4), single-use stream -> evict-first
    float4 p0 = __ldcs(&preds4[pbase]);
    float4 p1 = __ldcs(&preds4[pbase + 1u * PRED_BS4_]);
    float4 p2 = __ldcs(&preds4[pbase + 2u * PRED_BS4_]);
    float4 p3 = __ldcs(&preds4[pbase + 3u * PRED_BS4_]);
    float4 h  = __ldg (&heat4 [(size_t)b * SLICE4_ + rem]);
    float4 mk = __ldg (&masks4[(size_t)b * HW4_ + (rem & (HW4_ - 1u))]);

    float d0, d1, d2, d3;
    float det = 0.0f;
    d0 = p0.x - h.x; d1 = p0.y - h.y; d2 = p0.z - h.z; d3 = p0.w - h.w;
    det += d0 * d0 * mk.x + d1 * d1 * mk.y + d2 * d2 * mk.z + d3 * d3 * mk.w;
    d0 = p1.x - h.x; d1 = p1.y - h.y; d2 = p1.z - h.z; d3 = p1.w - h.w;
    det += d0 * d0 * mk.x + d1 * d1 * mk.y + d2 * d2 * mk.z + d3 * d3 * mk.w;
    d0 = p2.x - h.x; d1 = p2.y - h.y; d2 = p2.z - h.z; d3 = p2.w - h.w;
    det += d0 * d0 * mk.x + d1 * d1 * mk.y + d2 * d2 * mk.z + d3 * d3 * mk.w;
    d0 = p3.x - h.x; d1 = p3.y - h.y; d2 = p3.z - h.z; d3 = p3.w - h.w;
    det += d0 * d0 * mk.x + d1 * d1 * mk.y + d2 * d2 * mk.z + d3 * d3 * mk.w;

    // ---- tag part: one gather per low-gtid thread ----
    float tag = 0.0f;
    if (gtid < TAG_ITEMS) {
        unsigned t = gtid;
        unsigned p = t % 17u;
        unsigned m = (t / 17u) % 30u;
        unsigned s = (t / 510u) % 4u;
        unsigned bb = t / 2040u;
        unsigned kofs = (bb * 30u + m) * 17u + p;  // (B,M,P) layout
        unsigned l = (unsigned)kidx[kofs];         // flattened tag-map index [0, NP*HW)
        size_t addr = ((size_t)(bb * 4u + s) * C_ + NP_) * (size_t)HW_ + (size_t)l;
        float pv  = __ldg(preds + addr);
        float g   = gtags[kofs];   // tag_dim==1: (B,1,M,P) == (B,M,P)
        float vis = kvis[kofs];
        float d = pv - g;
        tag = d * d * vis;
    }

    const float DET_SCALE = 1.0f / DET_ELEMS;          // HM_W=1
    const float TAG_SCALE = 0.001f / (float)(B_ * S_); // TAG_W / (B*S)
    float val = det * DET_SCALE + tag * TAG_SCALE;

    // ---- block reduction ----
#pragma unroll
    for (int o = 16; o > 0; o >>= 1)
        val += __shfl_xor_sync(0xffffffffu, val, o);

    __shared__ float ws[NTHR / 32];
    if ((threadIdx.x & 31u) == 0u) ws[threadIdx.x >> 5] = val;
    __syncthreads();

    // one fire-and-forget global atomic per block; no fence, no ticket
    if (threadIdx.x == 0) {
        float x = ws[0];
#pragma unroll
        for (int i = 1; i < NTHR / 32; ++i) x += ws[i];
        atomicAdd(out, x);
    }
}

extern "C" void kernel_launch(void* const* d_in, const int* in_sizes, int n_in,
                              void* d_out, int out_size)
{
    const float4* preds4 = (const float4*)d_in[0];
    const float4* masks4 = (const float4*)d_in[1];
    const int*    kidx   = (const int*)d_in[2];
    const float*  kvis   = (const float*)d_in[3];
    const float*  gtags  = (const float*)d_in[4];
    const float4* heat4  = (const float4*)d_in[5];
    const float*  preds  = (const float*)d_in[0];
    float*        out    = (float*)d_out;

    init_out_kernel<<<1, 1>>>(out);
    loss_fused_kernel<<<NBLK, NTHR>>>(preds4, masks4, kidx, kvis, gtags, heat4, preds, out);
}